// round 6
// baseline (speedup 1.0000x reference)
#include <cuda_runtime.h>

// DWT_2D Haar: x [16,64,256,256] f32 -> (LL,LH,HL,HH) each [16,64,128,128]
// Each band pixel = +-sum of a disjoint 2x2 input block * 0.5. Pure stream.
//
// R6: fully-coalesced warp layout. One warp = one input row-pair (one image).
//   lane l loads r0[l], r0[l+32], r1[l], r1[l+32]  (4x LDG.128, each a
//   contiguous 512B warp transaction, 100% sector utilization)
//   lane l writes output cols {2l,2l+1} and {64+2l,64+2l+1} per band
//   (2x STG.64 per band, each a contiguous 256B warp transaction).
// Same thread count / bytes / flops as R3; only the lane->address map changes.

static constexpr int NIMG      = 16 * 64;          // 1024
static constexpr int IN_IMG    = 256 * 256;        // 65536 floats
static constexpr int OUT_IMG   = 128 * 128;        // 16384 floats
static constexpr long long BAND_STRIDE = (long long)NIMG * OUT_IMG; // 16777216

__device__ __forceinline__ void haar2(const float4& p, const float4& q,
                                      float2& ll, float2& lh, float2& hl, float2& hh)
{
    // p = 4 consecutive top-row floats, q = bottom row -> 2 output cols
    float sab0 = p.x + p.y, dab0 = p.x - p.y;
    float scd0 = q.x + q.y, dcd0 = q.x - q.y;
    float sab1 = p.z + p.w, dab1 = p.z - p.w;
    float scd1 = q.z + q.w, dcd1 = q.z - q.w;
    ll.x = 0.5f * (sab0 + scd0);  ll.y = 0.5f * (sab1 + scd1);
    lh.x = 0.5f * (dab0 + dcd0);  lh.y = 0.5f * (dab1 + dcd1);
    hl.x = 0.5f * (sab0 - scd0);  hl.y = 0.5f * (sab1 - scd1);
    hh.x = 0.5f * (dab0 - dcd0);  hh.y = 0.5f * (dab1 - dcd1);
}

__global__ __launch_bounds__(256)
void dwt2d_haar_kernel(const float* __restrict__ x, float* __restrict__ out)
{
    int t    = blockIdx.x * blockDim.x + threadIdx.x;
    int lane = t & 31;
    int w    = t >> 5;          // warp id: [n (1024)] [i (128)]
    int i    = w & 127;         // output row
    int n    = w >> 7;          // image index

    const float4* __restrict__ r0 =
        reinterpret_cast<const float4*>(x + (long long)n * IN_IMG + (long long)(2 * i)     * 256);
    const float4* __restrict__ r1 =
        reinterpret_cast<const float4*>(x + (long long)n * IN_IMG + (long long)(2 * i + 1) * 256);

    // 4 perfectly-coalesced LDG.128 (512B contiguous per warp each)
    float4 pA = r0[lane];        // top row, cols [4l, 4l+4)
    float4 pB = r0[lane + 32];   // top row, cols [128+4l, 128+4l+4)
    float4 qA = r1[lane];        // bottom row
    float4 qB = r1[lane + 32];

    float2 llA, lhA, hlA, hhA;   // output cols 2l, 2l+1
    float2 llB, lhB, hlB, hhB;   // output cols 64+2l, 64+2l+1
    haar2(pA, qA, llA, lhA, hlA, hhA);
    haar2(pB, qB, llB, lhB, hlB, hhB);

    // float2 units: output row base
    long long ob2 = (long long)n * (OUT_IMG / 2) + (long long)i * 64 + lane;
    float2* __restrict__ o2 = reinterpret_cast<float2*>(out) + ob2;
    const long long bs2 = BAND_STRIDE >> 1;   // band stride in float2 units

    // 8 coalesced STG.64 (256B contiguous per warp each)
    __stcs(o2,                llA);  __stcs(o2 + 32,           llB);  // LL
    __stcs(o2 + bs2,          lhA);  __stcs(o2 + bs2 + 32,     lhB);  // LH
    __stcs(o2 + 2 * bs2,      hlA);  __stcs(o2 + 2 * bs2 + 32, hlB);  // HL
    __stcs(o2 + 3 * bs2,      hhA);  __stcs(o2 + 3 * bs2 + 32, hhB);  // HH
}

extern "C" void kernel_launch(void* const* d_in, const int* in_sizes, int n_in,
                              void* d_out, int out_size)
{
    const float* x = (const float*)d_in[0];   // [16,64,256,256] f32
    // d_in[1..4] are the Haar DWT matrices -- algebraically folded, unused.
    float* out = (float*)d_out;               // 4 x [16,64,128,128] f32 concat

    // total threads = 1024 images * 128 rows * 32 lanes = 4,194,304
    int threads = 256;
    int blocks  = (NIMG * 128 * 32) / threads;  // 16384
    dwt2d_haar_kernel<<<blocks, threads>>>(x, out);
}